// round 4
// baseline (speedup 1.0000x reference)
#include <cuda_runtime.h>
#include <cstddef>

typedef unsigned long long ull;

// ---------------- scratch (static device globals; no allocation) ----------------
__device__ float g_h64[4096 * 64];     // LSTM1 final hidden
__device__ float g_h256[4096 * 256];   // LSTM2 hidden

// ---------------- packed f32x2 helpers ----------------
__device__ __forceinline__ ull pk(float lo, float hi) {
    ull r;
    asm("mov.b64 %0, {%1, %2};" : "=l"(r) : "f"(lo), "f"(hi));
    return r;
}
__device__ __forceinline__ void fma2(ull& d, ull a, ull b) {
    asm("fma.rn.f32x2 %0, %1, %2, %0;" : "+l"(d) : "l"(a), "l"(b));
}
__device__ __forceinline__ float2 upk(ull v) {
    float2 r;
    asm("mov.b64 {%0, %1}, %2;" : "=f"(r.x), "=f"(r.y) : "l"(v));
    return r;
}

// accurate activations (expf ~2ulp) — measured rel_err 2e-6 with these
__device__ __forceinline__ float sigf(float x) {
    return __fdividef(1.0f, 1.0f + __expf(-x));
}
__device__ __forceinline__ float tanh_(float x) {
    return __fdividef(2.0f, 1.0f + __expf(-2.0f * x)) - 1.0f;
}

// ---------------- shared layout for LSTM1 (floats) ----------------
// Wsh  [84][256]        : 21504   (k-major, gate columns i|f|g|o each 64 wide)
// actA [84][68]         :  5712   (rows 0..19 emb, 20..83 h; entries DUPLICATED: [2b],[2b+1])
// actB [84][68]         :  5712
// bsh  [256]            :   256
// eW   [64]             :    64   (W_embed, 40 used)
#define S1_WSH   0
#define S1_ACT0  21504
#define S1_ACT1  (21504 + 5712)
#define S1_BSH   (21504 + 2 * 5712)
#define S1_EW    (S1_BSH + 256)
#define S1_FLOATS (S1_EW + 64)          // 33248 floats = 132992 bytes
#define AROW 68                          // act row stride (64 dup + 4 pad, 16B-aligned)

__global__ void __launch_bounds__(512, 1)
lstm1_kernel(const float* __restrict__ x,
             const float* __restrict__ W_embed,
             const float* __restrict__ Wih1,
             const float* __restrict__ Whh1,
             const float* __restrict__ b1)
{
    extern __shared__ float sm[];
    float* Wsh  = sm + S1_WSH;
    float* act0 = sm + S1_ACT0;
    float* act1 = sm + S1_ACT1;
    float* bsh  = sm + S1_BSH;
    float* eW   = sm + S1_EW;

    const int tid = threadIdx.x;
    const int bt  = blockIdx.x;          // batch tile (32 elems)

    // combined weight [k][gate]: k<20 -> Wih1[g][k], else Whh1[g][k-20]
    for (int idx = tid; idx < 84 * 256; idx += 512) {
        int k = idx >> 8, g = idx & 255;
        Wsh[idx] = (k < 20) ? __ldg(&Wih1[g * 20 + k])
                            : __ldg(&Whh1[g * 64 + (k - 20)]);
    }
    if (tid < 256) bsh[tid] = b1[tid];
    if (tid < 40)  eW[tid]  = W_embed[tid];
    // zero h rows of act0 (incl. dup slots + pad)
    for (int idx = tid; idx < 64 * AROW; idx += 512) act0[20 * AROW + idx] = 0.0f;
    __syncthreads();

    // token stream for this lane's batch element (warp 0 handles embedding)
    const float2* xrow = reinterpret_cast<const float2*>(x) +
                         (size_t)(bt * 32 + (tid & 31)) * 512;
    float2 tok_next = make_float2(0.0f, 0.0f);
    if (tid < 32) {
        float2 t0 = xrow[0];
        #pragma unroll
        for (int e = 0; e < 20; e++) {
            float v = fmaxf(fmaf(t0.x, eW[2 * e], t0.y * eW[2 * e + 1]), 0.0f);
            *reinterpret_cast<float2*>(act0 + e * AROW + 2 * (tid & 31)) =
                make_float2(v, v);
        }
        tok_next = xrow[1];
    }
    __syncthreads();

    // mapping: warp w -> (batch octet bo, j-quarter jq); lane -> (j-pair m, batch-pair s)
    const int w  = tid >> 5, l = tid & 31;
    const int bo = w & 3, jq = w >> 2;
    const int m  = l & 7,  s  = l >> 3;
    const int j0 = jq * 16 + 2 * m;      // gate index pair (j0, j0+1), j in [0,64)
    const int b0 = bo * 8 + 2 * s;       // batch pair (b0, b0+1)

    const ull bI = pk(bsh[j0],        bsh[j0 + 1]);
    const ull bF = pk(bsh[64 + j0],   bsh[64 + j0 + 1]);
    const ull bG = pk(bsh[128 + j0],  bsh[128 + j0 + 1]);
    const ull bO = pk(bsh[192 + j0],  bsh[192 + j0 + 1]);

    // cell state lives in registers for the whole sequence
    float c00 = 0.f, c01 = 0.f, c10 = 0.f, c11 = 0.f;  // (b,j): 00=(b0,j0) 01=(b0,j1) 10=(b1,j0) 11=(b1,j1)

    const float* wbase = Wsh + j0;

    for (int t = 0; t < 512; t++) {
        float* cur = (t & 1) ? act1 : act0;
        float* nxt = (t & 1) ? act0 : act1;

        ull aI0 = bI, aI1 = bI, aF0 = bF, aF1 = bF;
        ull aG0 = bG, aG1 = bG, aO0 = bO, aO1 = bO;

        const float* abase = cur + 2 * b0;
        #pragma unroll
        for (int k = 0; k < 84; k++) {
            // duplicated act: one LDS.128 -> two ready f32x2 broadcast operands
            ulonglong2 av = *reinterpret_cast<const ulonglong2*>(abase + k * AROW);
            ull wI = *reinterpret_cast<const ull*>(wbase + k * 256);
            ull wF = *reinterpret_cast<const ull*>(wbase + k * 256 + 64);
            ull wG = *reinterpret_cast<const ull*>(wbase + k * 256 + 128);
            ull wO = *reinterpret_cast<const ull*>(wbase + k * 256 + 192);
            fma2(aI0, wI, av.x); fma2(aI1, wI, av.y);
            fma2(aF0, wF, av.x); fma2(aF1, wF, av.y);
            fma2(aG0, wG, av.x); fma2(aG1, wG, av.y);
            fma2(aO0, wO, av.x); fma2(aO1, wO, av.y);
        }

        // fused pointwise (lane-private, no spill)
        float2 vi0 = upk(aI0), vi1 = upk(aI1);
        float2 vf0 = upk(aF0), vf1 = upk(aF1);
        float2 vg0 = upk(aG0), vg1 = upk(aG1);
        float2 vo0 = upk(aO0), vo1 = upk(aO1);

        c00 = fmaf(sigf(vf0.x), c00, sigf(vi0.x) * tanh_(vg0.x));
        float h00 = sigf(vo0.x) * tanh_(c00);
        c01 = fmaf(sigf(vf0.y), c01, sigf(vi0.y) * tanh_(vg0.y));
        float h01 = sigf(vo0.y) * tanh_(c01);
        c10 = fmaf(sigf(vf1.x), c10, sigf(vi1.x) * tanh_(vg1.x));
        float h10 = sigf(vo1.x) * tanh_(c10);
        c11 = fmaf(sigf(vf1.y), c11, sigf(vi1.y) * tanh_(vg1.y));
        float h11 = sigf(vo1.y) * tanh_(c11);

        // write duplicated h into next buffer (2x STS.128)
        *reinterpret_cast<float4*>(nxt + (20 + j0) * AROW + 2 * b0) =
            make_float4(h00, h00, h10, h10);
        *reinterpret_cast<float4*>(nxt + (21 + j0) * AROW + 2 * b0) =
            make_float4(h01, h01, h11, h11);

        // embedding for t+1 (warp 0), token prefetched a full step ahead
        if (tid < 32 && t < 511) {
            #pragma unroll
            for (int e = 0; e < 20; e++) {
                float v = fmaxf(fmaf(tok_next.x, eW[2 * e],
                                     tok_next.y * eW[2 * e + 1]), 0.0f);
                *reinterpret_cast<float2*>(nxt + e * AROW + 2 * (tid & 31)) =
                    make_float2(v, v);
            }
            if (t < 510) tok_next = xrow[t + 2];
        }
        __syncthreads();
    }

    // final h (step 512) was written into act0 (t=511 odd -> nxt=act0)
    for (int idx = tid; idx < 2048; idx += 512) {
        int bb = idx >> 6, j = idx & 63;
        g_h64[(size_t)(bt * 32 + bb) * 64 + j] = act0[(20 + j) * AROW + 2 * bb];
    }
}

// ---------------- LSTM2: single step, zero state -> f gate & Whh2 unused ----------------
// shared: Ws[3][64][256] = 49152 floats, hact[64][32] = 2048 floats -> 204800 B
__global__ void __launch_bounds__(256, 1)
lstm2_kernel(const float* __restrict__ Wih2, const float* __restrict__ b2)
{
    extern __shared__ float sm[];
    float* Ws   = sm;            // [type][k][j], type 0:i 1:g 2:o
    float* hact = sm + 49152;    // [k][b]
    const int tid = threadIdx.x;
    const int bt  = blockIdx.x;

    for (int idx = tid; idx < 3 * 64 * 256; idx += 256) {
        int tt = idx >> 14;
        int r  = idx & 16383;
        int k  = r >> 8, j = r & 255;
        int o  = (tt == 0) ? 0 : (tt == 1) ? 512 : 768;  // i, g, o gate offsets
        Ws[idx] = __ldg(&Wih2[(size_t)(o + j) * 64 + k]);
    }
    for (int idx = tid; idx < 2048; idx += 256) {
        int bb = idx >> 6, k = idx & 63;
        hact[k * 32 + bb] = g_h64[(size_t)(bt * 32 + bb) * 64 + k];
    }
    __syncthreads();

    const int w = tid >> 5, l = tid & 31;   // warp -> 4 batches, lane -> j pair
    for (int jc = 0; jc < 4; jc++) {
        int j = jc * 64 + 2 * l;
        ull bI = pk(__ldg(&b2[j]),       __ldg(&b2[j + 1]));
        ull bG = pk(__ldg(&b2[512 + j]), __ldg(&b2[512 + j + 1]));
        ull bO = pk(__ldg(&b2[768 + j]), __ldg(&b2[768 + j + 1]));
        ull aI[4], aG[4], aO[4];
        #pragma unroll
        for (int q = 0; q < 4; q++) { aI[q] = bI; aG[q] = bG; aO[q] = bO; }

        #pragma unroll 4
        for (int k = 0; k < 64; k++) {
            float4 a = *reinterpret_cast<const float4*>(hact + k * 32 + 4 * w);
            ull a0 = pk(a.x, a.x), a1 = pk(a.y, a.y);
            ull a2 = pk(a.z, a.z), a3 = pk(a.w, a.w);
            float2 wi = *reinterpret_cast<const float2*>(Ws + k * 256 + j);
            float2 wg = *reinterpret_cast<const float2*>(Ws + 16384 + k * 256 + j);
            float2 wo = *reinterpret_cast<const float2*>(Ws + 32768 + k * 256 + j);
            ull wpi = pk(wi.x, wi.y), wpg = pk(wg.x, wg.y), wpo = pk(wo.x, wo.y);
            fma2(aI[0], wpi, a0); fma2(aI[1], wpi, a1);
            fma2(aI[2], wpi, a2); fma2(aI[3], wpi, a3);
            fma2(aG[0], wpg, a0); fma2(aG[1], wpg, a1);
            fma2(aG[2], wpg, a2); fma2(aG[3], wpg, a3);
            fma2(aO[0], wpo, a0); fma2(aO[1], wpo, a1);
            fma2(aO[2], wpo, a2); fma2(aO[3], wpo, a3);
        }
        #pragma unroll
        for (int q = 0; q < 4; q++) {
            float2 vi = upk(aI[q]);
            float2 vg = upk(aG[q]);
            float2 vo = upk(aO[q]);
            float c0 = sigf(vi.x) * tanh_(vg.x);
            float h0 = sigf(vo.x) * tanh_(c0);
            float c1 = sigf(vi.y) * tanh_(vg.y);
            float h1 = sigf(vo.y) * tanh_(c1);
            int bb = bt * 32 + 4 * w + q;
            *reinterpret_cast<float2*>(&g_h256[(size_t)bb * 256 + j]) =
                make_float2(h0, h1);
        }
    }
}

// ---------------- output projection: out = h256 @ Wout^T + bout ----------------
__global__ void __launch_bounds__(256)
out_kernel(const float* __restrict__ Wout, const float* __restrict__ bout,
           float* __restrict__ out)
{
    int gw = (blockIdx.x * 256 + threadIdx.x) >> 5;   // one warp per batch elem
    int l  = threadIdx.x & 31;
    if (gw >= 4096) return;
    const float* hrow = g_h256 + (size_t)gw * 256;
    float p0 = 0.0f, p1 = 0.0f;
    #pragma unroll
    for (int m = 0; m < 8; m++) {
        int j = l + 32 * m;
        float h = hrow[j];
        p0 = fmaf(h, __ldg(&Wout[j]), p0);
        p1 = fmaf(h, __ldg(&Wout[256 + j]), p1);
    }
    #pragma unroll
    for (int s = 16; s > 0; s >>= 1) {
        p0 += __shfl_xor_sync(0xffffffffu, p0, s);
        p1 += __shfl_xor_sync(0xffffffffu, p1, s);
    }
    if (l == 0) {
        out[gw * 2]     = p0 + __ldg(&bout[0]);
        out[gw * 2 + 1] = p1 + __ldg(&bout[1]);
    }
}

// ---------------- launch ----------------
extern "C" void kernel_launch(void* const* d_in, const int* in_sizes, int n_in,
                              void* d_out, int out_size)
{
    // map inputs by unique element counts (robust to ordering)
    const float *x = nullptr, *W_embed = nullptr, *Wih1 = nullptr, *Whh1 = nullptr,
                *b1 = nullptr, *Wih2 = nullptr, *b2 = nullptr,
                *Wout = nullptr, *bout = nullptr;
    for (int i = 0; i < n_in; i++) {
        const float* p = (const float*)d_in[i];
        switch (in_sizes[i]) {
            case 4194304: x = p; break;        // (4096, 1024)
            case 40:      W_embed = p; break;  // (20, 2)
            case 5120:    Wih1 = p; break;     // (256, 20)
            case 16384:   Whh1 = p; break;     // (256, 64)
            case 256:     b1 = p; break;       // (256,)
            case 65536:   Wih2 = p; break;     // (1024, 64)
            case 262144:  /* Whh2 unused */ break;
            case 1024:    b2 = p; break;       // (1024,)
            case 512:     Wout = p; break;     // (2, 256)
            case 2:       bout = p; break;     // (2,)
            default: break;
        }
    }
    float* out = (float*)d_out;

    const int SMEM1 = S1_FLOATS * 4;          // 132992 B
    const int SMEM2 = (49152 + 2048) * 4;     // 204800 B
    cudaFuncSetAttribute(lstm1_kernel, cudaFuncAttributeMaxDynamicSharedMemorySize, SMEM1);
    cudaFuncSetAttribute(lstm2_kernel, cudaFuncAttributeMaxDynamicSharedMemorySize, SMEM2);

    lstm1_kernel<<<128, 512, SMEM1>>>(x, W_embed, Wih1, Whh1, b1);
    lstm2_kernel<<<128, 256, SMEM2>>>(Wih2, b2);
    out_kernel<<<512, 256>>>(Wout, bout, out);
    (void)out_size;
}

// round 5
// speedup vs baseline: 1.4676x; 1.4676x over previous
#include <cuda_runtime.h>
#include <cstddef>

typedef unsigned long long ull;

// ---------------- scratch (static device globals; no allocation) ----------------
__device__ float g_h64[4096 * 64];     // LSTM1 final hidden
__device__ float g_h256[4096 * 256];   // LSTM2 hidden

// ---------------- packed f32x2 helpers ----------------
__device__ __forceinline__ ull pk(float lo, float hi) {
    ull r;
    asm("mov.b64 %0, {%1, %2};" : "=l"(r) : "f"(lo), "f"(hi));
    return r;
}
__device__ __forceinline__ void fma2(ull& d, ull a, ull b) {
    asm("fma.rn.f32x2 %0, %1, %2, %0;" : "+l"(d) : "l"(a), "l"(b));
}
__device__ __forceinline__ float2 upk(ull v) {
    float2 r;
    asm("mov.b64 {%0, %1}, %2;" : "=f"(r.x), "=f"(r.y) : "l"(v));
    return r;
}

// accurate activations (expf ~2ulp) — measured rel_err 2e-6 with these
__device__ __forceinline__ float sigf(float x) {
    return __fdividef(1.0f, 1.0f + __expf(-x));
}
__device__ __forceinline__ float tanh_(float x) {
    return __fdividef(2.0f, 1.0f + __expf(-2.0f * x)) - 1.0f;
}

// ---------------- shared layout for LSTM1 (floats) ----------------
// Wsh  [84][256]        : 21504   (k-major; column = type*64 + j, types i|f|g|o)
// actA [84][68]         :  5712   (rows 0..19 emb, 20..83 h; DUPLICATED: [2b],[2b+1])
// actB [84][68]         :  5712
// bsh  [256]            :   256
// eW   [64]             :    64   (W_embed, 40 used)
#define S1_WSH   0
#define S1_ACT0  21504
#define S1_ACT1  (21504 + 5712)
#define S1_BSH   (21504 + 2 * 5712)
#define S1_EW    (S1_BSH + 256)
#define S1_FLOATS (S1_EW + 64)          // 33248 floats = 132992 bytes
#define AROW 68                          // act row stride (64 dup + 4 pad, 16B-aligned)

__global__ void __launch_bounds__(256, 1)
lstm1_kernel(const float* __restrict__ x,
             const float* __restrict__ W_embed,
             const float* __restrict__ Wih1,
             const float* __restrict__ Whh1,
             const float* __restrict__ b1)
{
    extern __shared__ float sm[];
    float* Wsh  = sm + S1_WSH;
    float* act0 = sm + S1_ACT0;
    float* act1 = sm + S1_ACT1;
    float* bsh  = sm + S1_BSH;
    float* eW   = sm + S1_EW;

    const int tid = threadIdx.x;
    const int bt  = blockIdx.x;          // batch tile (32 elems)

    // combined weight [k][col]: col = gate index (i|f|g|o each 64 wide)
    for (int idx = tid; idx < 84 * 256; idx += 256) {
        int k = idx >> 8, g = idx & 255;
        Wsh[idx] = (k < 20) ? __ldg(&Wih1[g * 20 + k])
                            : __ldg(&Whh1[g * 64 + (k - 20)]);
    }
    bsh[tid] = b1[tid];
    if (tid < 40) eW[tid] = W_embed[tid];
    // zero h rows of act0 (incl. dup slots + pad)
    for (int idx = tid; idx < 64 * AROW; idx += 256) act0[20 * AROW + idx] = 0.0f;
    __syncthreads();

    // ---- mapping ----
    // warp w -> batch octet g2 = w&3 (batches 8*g2 .. +7), j-half jh = w>>2
    // lane  -> j-pair j0 = jh*32 + 2*(l&15); batch quad b0 = 8*g2 + 4*(l>>4)
    const int w  = tid >> 5, l = tid & 31;
    const int g2 = w & 3,  jh = w >> 2;
    const int j0 = jh * 32 + 2 * (l & 15);
    const int b0 = g2 * 8 + 4 * (l >> 4);

    const float* wIb = Wsh + j0;          // type i: col j0
    const float* wFb = Wsh + 64 + j0;
    const float* wGb = Wsh + 128 + j0;
    const float* wOb = Wsh + 192 + j0;

    const ull bI = pk(bsh[j0],        bsh[j0 + 1]);
    const ull bF = pk(bsh[64 + j0],   bsh[64 + j0 + 1]);
    const ull bG = pk(bsh[128 + j0],  bsh[128 + j0 + 1]);
    const ull bO = pk(bsh[192 + j0],  bsh[192 + j0 + 1]);

    // register-resident cell state: c[b (0..3)][j (0..1)]
    float c0x=0.f,c0y=0.f,c1x=0.f,c1y=0.f,c2x=0.f,c2y=0.f,c3x=0.f,c3y=0.f;

    // embedding duty: each warp owns 4 batches: eb0
    const int eb0 = g2 * 8 + jh * 4;
    const float2* xrow = reinterpret_cast<const float2*>(x) +
                         (size_t)(bt * 32 + eb0 + l) * 512;   // valid for l<4
    float2 tok = make_float2(0.f, 0.f), tok_nxt = make_float2(0.f, 0.f);
    if (l < 4) tok = xrow[0];
    // initial embedding (t=0) into act0
    #pragma unroll
    for (int b = 0; b < 4; b++) {
        float tx = __shfl_sync(0xffffffffu, tok.x, b);
        float ty = __shfl_sync(0xffffffffu, tok.y, b);
        if (l < 20) {
            float v = fmaxf(fmaf(tx, eW[2 * l], ty * eW[2 * l + 1]), 0.0f);
            *reinterpret_cast<float2*>(act0 + l * AROW + 2 * (eb0 + b)) =
                make_float2(v, v);
        }
    }
    if (l < 4) tok_nxt = xrow[1];
    __syncthreads();

    for (int t = 0; t < 512; t++) {
        float* cur = (t & 1) ? act1 : act0;
        float* nxt = (t & 1) ? act0 : act1;

        ull aI0=bI,aI1=bI,aI2=bI,aI3=bI;
        ull aF0=bF,aF1=bF,aF2=bF,aF3=bF;
        ull aG0=bG,aG1=bG,aG2=bG,aG3=bG;
        ull aO0=bO,aO1=bO,aO2=bO,aO3=bO;

        const float* ab = cur + 2 * b0;
        #pragma unroll 21
        for (int k = 0; k < 84; k++) {
            // duplicated act: each LDS.128 -> two ready f32x2 broadcast operands
            ulonglong2 a01 = *reinterpret_cast<const ulonglong2*>(ab + k * AROW);
            ulonglong2 a23 = *reinterpret_cast<const ulonglong2*>(ab + k * AROW + 4);
            ull wi = *reinterpret_cast<const ull*>(wIb + k * 256);
            ull wf = *reinterpret_cast<const ull*>(wFb + k * 256);
            ull wg = *reinterpret_cast<const ull*>(wGb + k * 256);
            ull wo = *reinterpret_cast<const ull*>(wOb + k * 256);
            fma2(aI0, wi, a01.x); fma2(aI1, wi, a01.y);
            fma2(aI2, wi, a23.x); fma2(aI3, wi, a23.y);
            fma2(aF0, wf, a01.x); fma2(aF1, wf, a01.y);
            fma2(aF2, wf, a23.x); fma2(aF3, wf, a23.y);
            fma2(aG0, wg, a01.x); fma2(aG1, wg, a01.y);
            fma2(aG2, wg, a23.x); fma2(aG3, wg, a23.y);
            fma2(aO0, wo, a01.x); fma2(aO1, wo, a01.y);
            fma2(aO2, wo, a23.x); fma2(aO3, wo, a23.y);
        }

        // fused pointwise (lane-private; cell state in registers)
        float2 vi, vf, vg, vo;
        float h0x,h0y,h1x,h1y,h2x,h2y,h3x,h3y;
        vi=upk(aI0); vf=upk(aF0); vg=upk(aG0); vo=upk(aO0);
        c0x = fmaf(sigf(vf.x), c0x, sigf(vi.x) * tanh_(vg.x));
        h0x = sigf(vo.x) * tanh_(c0x);
        c0y = fmaf(sigf(vf.y), c0y, sigf(vi.y) * tanh_(vg.y));
        h0y = sigf(vo.y) * tanh_(c0y);
        vi=upk(aI1); vf=upk(aF1); vg=upk(aG1); vo=upk(aO1);
        c1x = fmaf(sigf(vf.x), c1x, sigf(vi.x) * tanh_(vg.x));
        h1x = sigf(vo.x) * tanh_(c1x);
        c1y = fmaf(sigf(vf.y), c1y, sigf(vi.y) * tanh_(vg.y));
        h1y = sigf(vo.y) * tanh_(c1y);
        vi=upk(aI2); vf=upk(aF2); vg=upk(aG2); vo=upk(aO2);
        c2x = fmaf(sigf(vf.x), c2x, sigf(vi.x) * tanh_(vg.x));
        h2x = sigf(vo.x) * tanh_(c2x);
        c2y = fmaf(sigf(vf.y), c2y, sigf(vi.y) * tanh_(vg.y));
        h2y = sigf(vo.y) * tanh_(c2y);
        vi=upk(aI3); vf=upk(aF3); vg=upk(aG3); vo=upk(aO3);
        c3x = fmaf(sigf(vf.x), c3x, sigf(vi.x) * tanh_(vg.x));
        h3x = sigf(vo.x) * tanh_(c3x);
        c3y = fmaf(sigf(vf.y), c3y, sigf(vi.y) * tanh_(vg.y));
        h3y = sigf(vo.y) * tanh_(c3y);

        // duplicated h stores: 4x STS.128 (batches b0..b0+3 contiguous)
        *reinterpret_cast<float4*>(nxt + (20 + j0) * AROW + 2 * b0) =
            make_float4(h0x, h0x, h1x, h1x);
        *reinterpret_cast<float4*>(nxt + (20 + j0) * AROW + 2 * b0 + 4) =
            make_float4(h2x, h2x, h3x, h3x);
        *reinterpret_cast<float4*>(nxt + (21 + j0) * AROW + 2 * b0) =
            make_float4(h0y, h0y, h1y, h1y);
        *reinterpret_cast<float4*>(nxt + (21 + j0) * AROW + 2 * b0 + 4) =
            make_float4(h2y, h2y, h3y, h3y);

        // per-warp embedding for t+1 (token prefetched a full step ahead)
        if (t < 511) {
            #pragma unroll
            for (int b = 0; b < 4; b++) {
                float tx = __shfl_sync(0xffffffffu, tok_nxt.x, b);
                float ty = __shfl_sync(0xffffffffu, tok_nxt.y, b);
                if (l < 20) {
                    float v = fmaxf(fmaf(tx, eW[2 * l], ty * eW[2 * l + 1]), 0.0f);
                    *reinterpret_cast<float2*>(nxt + l * AROW + 2 * (eb0 + b)) =
                        make_float2(v, v);
                }
            }
            if (l < 4 && t < 510) tok_nxt = xrow[t + 2];
        }
        __syncthreads();
    }

    // final h (after step 512) lives in act0 (t=511 odd -> nxt=act0)
    for (int idx = tid; idx < 2048; idx += 256) {
        int bb = idx >> 6, j = idx & 63;
        g_h64[(size_t)(bt * 32 + bb) * 64 + j] = act0[(20 + j) * AROW + 2 * bb];
    }
}

// ---------------- LSTM2: single step, zero state -> f gate & Whh2 unused ----------------
// shared: Ws[3][64][256] = 49152 floats, hact[64][32] = 2048 floats -> 204800 B
__global__ void __launch_bounds__(256, 1)
lstm2_kernel(const float* __restrict__ Wih2, const float* __restrict__ b2)
{
    extern __shared__ float sm[];
    float* Ws   = sm;            // [type][k][j], type 0:i 1:g 2:o
    float* hact = sm + 49152;    // [k][b]
    const int tid = threadIdx.x;
    const int bt  = blockIdx.x;

    for (int idx = tid; idx < 3 * 64 * 256; idx += 256) {
        int tt = idx >> 14;
        int r  = idx & 16383;
        int k  = r >> 8, j = r & 255;
        int o  = (tt == 0) ? 0 : (tt == 1) ? 512 : 768;  // i, g, o gate offsets
        Ws[idx] = __ldg(&Wih2[(size_t)(o + j) * 64 + k]);
    }
    for (int idx = tid; idx < 2048; idx += 256) {
        int bb = idx >> 6, k = idx & 63;
        hact[k * 32 + bb] = g_h64[(size_t)(bt * 32 + bb) * 64 + k];
    }
    __syncthreads();

    const int w = tid >> 5, l = tid & 31;   // warp -> 4 batches, lane -> j pair
    for (int jc = 0; jc < 4; jc++) {
        int j = jc * 64 + 2 * l;
        ull bI = pk(__ldg(&b2[j]),       __ldg(&b2[j + 1]));
        ull bG = pk(__ldg(&b2[512 + j]), __ldg(&b2[512 + j + 1]));
        ull bO = pk(__ldg(&b2[768 + j]), __ldg(&b2[768 + j + 1]));
        ull aI[4], aG[4], aO[4];
        #pragma unroll
        for (int q = 0; q < 4; q++) { aI[q] = bI; aG[q] = bG; aO[q] = bO; }

        #pragma unroll 4
        for (int k = 0; k < 64; k++) {
            float4 a = *reinterpret_cast<const float4*>(hact + k * 32 + 4 * w);
            ull a0 = pk(a.x, a.x), a1 = pk(a.y, a.y);
            ull a2 = pk(a.z, a.z), a3 = pk(a.w, a.w);
            float2 wi = *reinterpret_cast<const float2*>(Ws + k * 256 + j);
            float2 wg = *reinterpret_cast<const float2*>(Ws + 16384 + k * 256 + j);
            float2 wo = *reinterpret_cast<const float2*>(Ws + 32768 + k * 256 + j);
            ull wpi = pk(wi.x, wi.y), wpg = pk(wg.x, wg.y), wpo = pk(wo.x, wo.y);
            fma2(aI[0], wpi, a0); fma2(aI[1], wpi, a1);
            fma2(aI[2], wpi, a2); fma2(aI[3], wpi, a3);
            fma2(aG[0], wpg, a0); fma2(aG[1], wpg, a1);
            fma2(aG[2], wpg, a2); fma2(aG[3], wpg, a3);
            fma2(aO[0], wpo, a0); fma2(aO[1], wpo, a1);
            fma2(aO[2], wpo, a2); fma2(aO[3], wpo, a3);
        }
        #pragma unroll
        for (int q = 0; q < 4; q++) {
            float2 vi = upk(aI[q]);
            float2 vg = upk(aG[q]);
            float2 vo = upk(aO[q]);
            float c0 = sigf(vi.x) * tanh_(vg.x);
            float h0 = sigf(vo.x) * tanh_(c0);
            float c1 = sigf(vi.y) * tanh_(vg.y);
            float h1 = sigf(vo.y) * tanh_(c1);
            int bb = bt * 32 + 4 * w + q;
            *reinterpret_cast<float2*>(&g_h256[(size_t)bb * 256 + j]) =
                make_float2(h0, h1);
        }
    }
}

// ---------------- output projection: out = h256 @ Wout^T + bout ----------------
__global__ void __launch_bounds__(256)
out_kernel(const float* __restrict__ Wout, const float* __restrict__ bout,
           float* __restrict__ out)
{
    int gw = (blockIdx.x * 256 + threadIdx.x) >> 5;   // one warp per batch elem
    int l  = threadIdx.x & 31;
    if (gw >= 4096) return;
    const float* hrow = g_h256 + (size_t)gw * 256;
    float p0 = 0.0f, p1 = 0.0f;
    #pragma unroll
    for (int m = 0; m < 8; m++) {
        int j = l + 32 * m;
        float h = hrow[j];
        p0 = fmaf(h, __ldg(&Wout[j]), p0);
        p1 = fmaf(h, __ldg(&Wout[256 + j]), p1);
    }
    #pragma unroll
    for (int s = 16; s > 0; s >>= 1) {
        p0 += __shfl_xor_sync(0xffffffffu, p0, s);
        p1 += __shfl_xor_sync(0xffffffffu, p1, s);
    }
    if (l == 0) {
        out[gw * 2]     = p0 + __ldg(&bout[0]);
        out[gw * 2 + 1] = p1 + __ldg(&bout[1]);
    }
}

// ---------------- launch ----------------
extern "C" void kernel_launch(void* const* d_in, const int* in_sizes, int n_in,
                              void* d_out, int out_size)
{
    // map inputs by unique element counts (robust to ordering)
    const float *x = nullptr, *W_embed = nullptr, *Wih1 = nullptr, *Whh1 = nullptr,
                *b1 = nullptr, *Wih2 = nullptr, *b2 = nullptr,
                *Wout = nullptr, *bout = nullptr;
    for (int i = 0; i < n_in; i++) {
        const float* p = (const float*)d_in[i];
        switch (in_sizes[i]) {
            case 4194304: x = p; break;        // (4096, 1024)
            case 40:      W_embed = p; break;  // (20, 2)
            case 5120:    Wih1 = p; break;     // (256, 20)
            case 16384:   Whh1 = p; break;     // (256, 64)
            case 256:     b1 = p; break;       // (256,)
            case 65536:   Wih2 = p; break;     // (1024, 64)
            case 262144:  /* Whh2 unused */ break;
            case 1024:    b2 = p; break;       // (1024,)
            case 512:     Wout = p; break;     // (2, 256)
            case 2:       bout = p; break;     // (2,)
            default: break;
        }
    }
    float* out = (float*)d_out;

    const int SMEM1 = S1_FLOATS * 4;          // 132992 B
    const int SMEM2 = (49152 + 2048) * 4;     // 204800 B
    cudaFuncSetAttribute(lstm1_kernel, cudaFuncAttributeMaxDynamicSharedMemorySize, SMEM1);
    cudaFuncSetAttribute(lstm2_kernel, cudaFuncAttributeMaxDynamicSharedMemorySize, SMEM2);

    lstm1_kernel<<<128, 256, SMEM1>>>(x, W_embed, Wih1, Whh1, b1);
    lstm2_kernel<<<128, 256, SMEM2>>>(Wih2, b2);
    out_kernel<<<512, 256>>>(Wout, bout, out);
    (void)out_size;
}